// round 14
// baseline (speedup 1.0000x reference)
#include <cuda_runtime.h>
#include <cuda_bf16.h>
#include <cstdint>
#include <cstddef>

#define BB    64
#define TKK   2048
#define HH    512
#define HH2   1024
#define EE    128
#define KCTX  1152      // 2H + E
#define VV    50000
#define VXX   50512     // V + NOOV
#define FINAL_N  (BB*VXX)
#define FINAL_BLOCKS (64*198)

// ---------------- scratch ----------------
__device__ __align__(16) float g_x[BB*EE];
__device__ __align__(16) float g_h[BB*HH];
__device__ __align__(16) float g_c[BB*HH];
__device__ __align__(16) float g_hc[BB*HH2];
__device__ __align__(16) float g_df[BB*HH2];
__device__ __align__(16) float g_scores[BB*TKK];
__device__ __align__(16) float g_attn[BB*TKK];
__device__ __align__(16) float g_ct[BB*HH2];
__device__ __align__(16) float g_out1[BB*HH];
__device__ float g_pgen[BB];
__device__ float g_scale[BB];
__device__ float g_vmax[BB];
__device__ float g_pm[256];
__device__ float g_ps[256];
__device__ __align__(16) float g_logits[BB*VV];

// ---------------- helpers ----------------
__device__ __forceinline__ float warpSum(float v) {
#pragma unroll
    for (int o = 16; o; o >>= 1) v += __shfl_xor_sync(0xffffffffu, v, o);
    return v;
}
__device__ __forceinline__ float warpMax(float v) {
#pragma unroll
    for (int o = 16; o; o >>= 1) v = fmaxf(v, __shfl_xor_sync(0xffffffffu, v, o));
    return v;
}
__device__ __forceinline__ float sigm(float x) { return 1.f / (1.f + __expf(-x)); }
__device__ __forceinline__ float htanh(float x) {   // HW tanh, 1 MUFU op
    float y;
    asm("tanh.approx.f32 %0, %1;" : "=f"(y) : "f"(x));
    return y;
}
__device__ __forceinline__ unsigned long long rep2(float v) {
    unsigned long long r;
    asm("mov.b64 %0, {%1,%1};" : "=l"(r) : "f"(v));
    return r;
}
__device__ __forceinline__ void fma2(unsigned long long& d, unsigned long long a, unsigned long long b) {
    asm("fma.rn.f32x2 %0, %1, %2, %0;" : "+l"(d) : "l"(a), "l"(b));
}
__device__ __forceinline__ void unpack2(unsigned long long p, float& lo, float& hi) {
    asm("mov.b64 {%0,%1}, %2;" : "=f"(lo), "=f"(hi) : "l"(p));
}

// ---------------- K1: x = concat(c_t_1, emb) @ W_ctx^T + b_ctx  [64,128] ----------------
__global__ void k_x(const int* __restrict__ ids, const float* __restrict__ ct1,
                    const float* __restrict__ W_emb, const float* __restrict__ W_ctx,
                    const float* __restrict__ b_ctx) {
    __shared__ float ws[KCTX];
    int e = blockIdx.x;
    for (int k = threadIdx.x; k < KCTX; k += 256) ws[k] = W_ctx[e * KCTX + k];
    __syncthreads();
    int warp = threadIdx.x >> 5, lane = threadIdx.x & 31;
    for (int b = warp; b < BB; b += 8) {
        int id = ids[b];
        float acc = 0.f;
        for (int k = lane; k < KCTX; k += 32) {
            float inv = (k < HH2) ? ct1[b * HH2 + k] : W_emb[(size_t)id * EE + (k - HH2)];
            acc += inv * ws[k];
        }
        acc = warpSum(acc);
        if (lane == 0) g_x[b * EE + e] = acc + b_ctx[e];
    }
}

// ---------------- K2: LSTM ----------------
__global__ void k_lstm(const float* __restrict__ h0, const float* __restrict__ c0,
                       const float* __restrict__ W_ih, const float* __restrict__ W_hh,
                       const float* __restrict__ b_ih, const float* __restrict__ b_hh) {
    __shared__ float s[64 * 129];
    int tid = threadIdx.x;
    int b = tid & 63, ty = tid >> 6;
    int j = blockIdx.x * 4 + ty;
    float ai = 0.f, af = 0.f, ag = 0.f, ao = 0.f;

    for (int i = tid; i < 64 * 128; i += 256) { int r = i >> 7, c = i & 127; s[r * 129 + c] = g_x[i]; }
    __syncthreads();
    {
        const float* wi = W_ih + (size_t)j * EE;
#pragma unroll 4
        for (int k = 0; k < EE; k++) {
            float xv = s[b * 129 + k];
            ai += xv * wi[k];
            af += xv * wi[(size_t)HH * EE + k];
            ag += xv * wi[(size_t)2 * HH * EE + k];
            ao += xv * wi[(size_t)3 * HH * EE + k];
        }
    }
    for (int kt = 0; kt < 4; kt++) {
        __syncthreads();
        for (int i = tid; i < 64 * 128; i += 256) {
            int r = i >> 7, c = i & 127;
            s[r * 129 + c] = h0[r * HH + kt * 128 + c];
        }
        __syncthreads();
        const float* wh = W_hh + (size_t)j * HH + kt * 128;
#pragma unroll 4
        for (int k = 0; k < 128; k++) {
            float hv = s[b * 129 + k];
            ai += hv * wh[k];
            af += hv * wh[(size_t)HH * HH + k];
            ag += hv * wh[(size_t)2 * HH * HH + k];
            ao += hv * wh[(size_t)3 * HH * HH + k];
        }
    }
    ai += b_ih[j]          + b_hh[j];
    af += b_ih[HH + j]     + b_hh[HH + j];
    ag += b_ih[2 * HH + j] + b_hh[2 * HH + j];
    ao += b_ih[3 * HH + j] + b_hh[3 * HH + j];

    float cprev = c0[b * HH + j];
    float cc = sigm(af) * cprev + sigm(ai) * tanhf(ag);
    float hh = sigm(ao) * tanhf(cc);
    g_c[b * HH + j] = cc;
    g_h[b * HH + j] = hh;
    g_hc[b * HH2 + j] = hh;
    g_hc[b * HH2 + HH + j] = cc;
}

// ---------------- K3: dec_feature (+ zero g_ct) ----------------
__global__ void k_attnfeat(const float* __restrict__ W_attn, const float* __restrict__ b_attn) {
    __shared__ float s[64 * 129];
    int tid = threadIdx.x;
    g_ct[blockIdx.x * 256 + tid] = 0.f;
    int b = tid & 63, ty = tid >> 6;
    int n = blockIdx.x * 4 + ty;
    float acc = 0.f;
    const float* w = W_attn + (size_t)n * HH2;
    for (int kt = 0; kt < 8; kt++) {
        __syncthreads();
        for (int i = tid; i < 64 * 128; i += 256) {
            int r = i >> 7, c = i & 127;
            s[r * 129 + c] = g_hc[r * HH2 + kt * 128 + c];
        }
        __syncthreads();
#pragma unroll 4
        for (int k = 0; k < 128; k++) acc += s[b * 129 + k] * w[kt * 128 + k];
    }
    g_df[b * HH2 + n] = acc + b_attn[n];
}

// ---------------- K4: scores (512MB stream), R12-proven ----------------
__global__ void __launch_bounds__(256) k_scores(const float4* __restrict__ ef4,
                                                const float* __restrict__ vat) {
    __shared__ float4 sdf[256];
    __shared__ float4 svv[256];
    int bb = blockIdx.x >> 4;
    int tc = blockIdx.x & 15;
    int tid = threadIdx.x;
    sdf[tid] = reinterpret_cast<const float4*>(g_df + bb * HH2)[tid];
    svv[tid] = reinterpret_cast<const float4*>(vat)[tid];
    __syncthreads();
    int warp = tid >> 5, lane = tid & 31;
    for (int r = 0; r < 16; r++) {
        int t = tc * 128 + warp * 16 + r;
        const float4* er = ef4 + ((size_t)(bb * TKK + t)) * 256;
        float acc = 0.f;
#pragma unroll
        for (int i = 0; i < 8; i++) {
            float4 e = er[i * 32 + lane];
            float4 d = sdf[i * 32 + lane];
            float4 v = svv[i * 32 + lane];
            acc += v.x * htanh(e.x + d.x);
            acc += v.y * htanh(e.y + d.y);
            acc += v.z * htanh(e.z + d.z);
            acc += v.w * htanh(e.w + d.w);
        }
        float s = warpSum(acc);
        if (lane == 0) g_scores[bb * TKK + t] = s;
    }
}

// ---------------- K5: c_t (512MB stream) with fused attention softmax (R12) ----------------
__global__ void __launch_bounds__(256) k_ct(const float4* __restrict__ eo4,
                                            const float* __restrict__ mask) {
    __shared__ float as[256];
    __shared__ float red[8];
    int b = blockIdx.x >> 3, tc = blockIdx.x & 7;
    int tid = threadIdx.x;
    int warp = tid >> 5, lane = tid & 31;
    const float* sc = g_scores + b * TKK;
    const float* mk = mask + b * TKK;

    float m = -3.4e38f;
    for (int t = tid; t < TKK; t += 256) m = fmaxf(m, sc[t]);
    m = warpMax(m);
    if (lane == 0) red[warp] = m;
    __syncthreads();
    float mm = red[0];
#pragma unroll
    for (int i = 1; i < 8; i++) mm = fmaxf(mm, red[i]);
    __syncthreads();
    float s = 0.f;
    for (int t = tid; t < TKK; t += 256) s += __expf(sc[t] - mm) * mk[t];
    s = warpSum(s);
    if (lane == 0) red[warp] = s;
    __syncthreads();
    float tot = 0.f;
#pragma unroll
    for (int i = 0; i < 8; i++) tot += red[i];
    float inv = 1.f / tot;

    int t0 = tc * 256;
    float av = __expf(sc[t0 + tid] - mm) * mk[t0 + tid] * inv;
    g_attn[b * TKK + t0 + tid] = av;
    as[tid] = av;
    __syncthreads();

    const float4* base = eo4 + ((size_t)(b * TKK + t0)) * 256 + tid;
    float4 a0 = make_float4(0.f,0.f,0.f,0.f), a1 = a0, a2 = a0, a3 = a0;
#pragma unroll 2
    for (int t = 0; t < 256; t += 4) {
        float4 e0 = base[(size_t)(t + 0) * 256];
        float4 e1 = base[(size_t)(t + 1) * 256];
        float4 e2 = base[(size_t)(t + 2) * 256];
        float4 e3 = base[(size_t)(t + 3) * 256];
        float w0 = as[t], w1 = as[t+1], w2 = as[t+2], w3 = as[t+3];
        a0.x += w0*e0.x; a0.y += w0*e0.y; a0.z += w0*e0.z; a0.w += w0*e0.w;
        a1.x += w1*e1.x; a1.y += w1*e1.y; a1.z += w1*e1.z; a1.w += w1*e1.w;
        a2.x += w2*e2.x; a2.y += w2*e2.y; a2.z += w2*e2.z; a2.w += w2*e2.w;
        a3.x += w3*e3.x; a3.y += w3*e3.y; a3.z += w3*e3.z; a3.w += w3*e3.w;
    }
    float* dst = g_ct + b * HH2 + tid * 4;
    atomicAdd(dst + 0, a0.x + a1.x + a2.x + a3.x);
    atomicAdd(dst + 1, a0.y + a1.y + a2.y + a3.y);
    atomicAdd(dst + 2, a0.z + a1.z + a2.z + a3.z);
    atomicAdd(dst + 3, a0.w + a1.w + a2.w + a3.w);
}

// ---------------- K6: out1 + p_gen ----------------
__global__ void k_out1(const float* __restrict__ W1, const float* __restrict__ b1,
                       const float* __restrict__ Wp, const float* __restrict__ bp) {
    __shared__ float s[64 * 129];
    int tid = threadIdx.x;
    if (blockIdx.x < 128) {
        int b = tid & 63, ty = tid >> 6;
        int m = blockIdx.x * 4 + ty;
        float acc = 0.f;
        const float* w = W1 + (size_t)m * 1536;
        for (int kt = 0; kt < 12; kt++) {
            __syncthreads();
            for (int i = tid; i < 64 * 128; i += 256) {
                int r = i >> 7, c = i & 127;
                int kk = kt * 128 + c;
                s[r * 129 + c] = (kk < HH) ? g_h[r * HH + kk] : g_ct[r * HH2 + kk - HH];
            }
            __syncthreads();
#pragma unroll 4
            for (int k = 0; k < 128; k++) acc += s[b * 129 + k] * w[kt * 128 + k];
        }
        g_out1[b * HH + m] = acc + b1[m];
    } else {
        int warp = tid >> 5, lane = tid & 31;
        for (int b = warp; b < BB; b += 8) {
            float acc = 0.f;
            for (int k = lane; k < 2176; k += 32) {
                float pv;
                if (k < HH2)       pv = g_ct[b * HH2 + k];
                else if (k < 2048) pv = g_hc[b * HH2 + (k - HH2)];
                else               pv = g_x[b * EE + (k - 2048)];
                acc += pv * Wp[k];
            }
            acc = warpSum(acc);
            if (lane == 0) g_pgen[b] = sigm(acc + bp[0]);
        }
    }
}

// ---------------- K7: logits = out1 @ W_out2^T + b_out2  [64, 50000] ----------------
__global__ void __launch_bounds__(256) k_logits(const float* __restrict__ W2,
                                                const float* __restrict__ b2) {
    __shared__ float s_x[64][72];     // [k][b]
    __shared__ float s_w[64][132];    // [k][v^swz(k)], swz=((k>>2)&7)<<2
    int tid = threadIdx.x;
    int warp = tid >> 5, lane = tid & 31;
    int v0 = blockIdx.x * 128;
    int half = lane >> 4, li = lane & 15;

    unsigned long long acc[4][4];
#pragma unroll
    for (int ip = 0; ip < 4; ip++)
#pragma unroll
        for (int j = 0; j < 4; j++) acc[ip][j] = 0ull;

    for (int k0 = 0; k0 < HH; k0 += 64) {
        __syncthreads();
        {
            int r = tid & 63, m = tid >> 6;
#pragma unroll
            for (int it = 0; it < 4; it++) {
                int c = m * 16 + it * 4;
                float4 xv = *reinterpret_cast<const float4*>(g_out1 + r * HH + k0 + c);
                s_x[c + 0][r] = xv.x; s_x[c + 1][r] = xv.y;
                s_x[c + 2][r] = xv.z; s_x[c + 3][r] = xv.w;
            }
        }
#pragma unroll
        for (int it = 0; it < 8; it++) {
            int row = it * 16 + warp * 2 + half;
            int vg = v0 + row;
            float4 wv = make_float4(0.f, 0.f, 0.f, 0.f);
            if (vg < VV) wv = *reinterpret_cast<const float4*>(W2 + (size_t)vg * HH + k0 + 4 * li);
            int sw = row ^ ((li & 7) << 2);
            s_w[4 * li + 0][sw] = wv.x; s_w[4 * li + 1][sw] = wv.y;
            s_w[4 * li + 2][sw] = wv.z; s_w[4 * li + 3][sw] = wv.w;
        }
        __syncthreads();
#pragma unroll 8
        for (int k = 0; k < 64; k++) {
            int swz = ((k >> 2) & 7) << 2;
            float4 w4 = *reinterpret_cast<const float4*>(&s_w[k][(4 * lane) ^ swz]);
            ulonglong2 xa = *reinterpret_cast<const ulonglong2*>(&s_x[k][warp * 8]);
            ulonglong2 xb = *reinterpret_cast<const ulonglong2*>(&s_x[k][warp * 8 + 4]);
            unsigned long long w0 = rep2(w4.x), w1 = rep2(w4.y), w2 = rep2(w4.z), w3 = rep2(w4.w);
            fma2(acc[0][0], xa.x, w0); fma2(acc[0][1], xa.x, w1); fma2(acc[0][2], xa.x, w2); fma2(acc[0][3], xa.x, w3);
            fma2(acc[1][0], xa.y, w0); fma2(acc[1][1], xa.y, w1); fma2(acc[1][2], xa.y, w2); fma2(acc[1][3], xa.y, w3);
            fma2(acc[2][0], xb.x, w0); fma2(acc[2][1], xb.x, w1); fma2(acc[2][2], xb.x, w2); fma2(acc[2][3], xb.x, w3);
            fma2(acc[3][0], xb.y, w0); fma2(acc[3][1], xb.y, w1); fma2(acc[3][2], xb.y, w2); fma2(acc[3][3], xb.y, w3);
        }
    }
    int v = v0 + 4 * lane;
    if (v < VV) {
        float4 bias = *reinterpret_cast<const float4*>(b2 + v);
#pragma unroll
        for (int ip = 0; ip < 4; ip++) {
            float lo0, hi0, lo1, hi1, lo2, hi2, lo3, hi3;
            unpack2(acc[ip][0], lo0, hi0); unpack2(acc[ip][1], lo1, hi1);
            unpack2(acc[ip][2], lo2, hi2); unpack2(acc[ip][3], lo3, hi3);
            int b = warp * 8 + 2 * ip;
            float4 r0 = make_float4(lo0 + bias.x, lo1 + bias.y, lo2 + bias.z, lo3 + bias.w);
            float4 r1 = make_float4(hi0 + bias.x, hi1 + bias.y, hi2 + bias.z, hi3 + bias.w);
            *reinterpret_cast<float4*>(g_logits + (size_t)b * VV + v)       = r0;
            *reinterpret_cast<float4*>(g_logits + (size_t)(b + 1) * VV + v) = r1;
        }
    }
}

// ---------------- K8a: partial vocab softmax stats ----------------
__global__ void k_vstats1() {
    __shared__ float sh[8];
    int b = blockIdx.x >> 2, q = blockIdx.x & 3;
    int tid = threadIdx.x, warp = tid >> 5, lane = tid & 31;
    const float* lg = g_logits + (size_t)b * VV;
    int lo = q * 12500, hi = lo + 12500;
    float m = -3.4e38f;
    for (int v = lo + tid; v < hi; v += 256) m = fmaxf(m, lg[v]);
    m = warpMax(m);
    if (lane == 0) sh[warp] = m;
    __syncthreads();
    float mm = sh[0];
#pragma unroll
    for (int i = 1; i < 8; i++) mm = fmaxf(mm, sh[i]);
    __syncthreads();
    float s = 0.f;
    for (int v = lo + tid; v < hi; v += 256) s += __expf(lg[v] - mm);
    s = warpSum(s);
    if (lane == 0) sh[warp] = s;
    __syncthreads();
    if (tid == 0) {
        float tot = 0.f;
#pragma unroll
        for (int i = 0; i < 8; i++) tot += sh[i];
        g_pm[blockIdx.x] = mm;
        g_ps[blockIdx.x] = tot;
    }
}

// ---------------- K8b: combine partials ----------------
__global__ void k_vstats2() {
    int b = blockIdx.x, lane = threadIdx.x;
    float pm = (lane < 4) ? g_pm[b * 4 + lane] : -3.4e38f;
    float mm = warpMax(pm);
    float ps = (lane < 4) ? g_ps[b * 4 + lane] * __expf(pm - mm) : 0.f;
    float tot = warpSum(ps);
    if (lane == 0) { g_vmax[b] = mm; g_scale[b] = g_pgen[b] / tot; }
}

// ---------------- K9: final vocab part + tail (merged) ----------------
__global__ void __launch_bounds__(256) k_final(float* __restrict__ out,
                                               const float* __restrict__ cov_in,
                                               int out_size) {
    int bid = blockIdx.x;
    if (bid < FINAL_BLOCKS) {
        int b = bid / 198;
        int v = (bid % 198) * 256 + threadIdx.x;
        if (v >= VXX) return;
        float val = 0.f;
        if (v < VV) val = __expf(g_logits[(size_t)b * VV + v] - g_vmax[b]) * g_scale[b];
        out[(size_t)b * VXX + v] = val;
    } else {
        int i = (bid - FINAL_BLOCKS) * 256 + threadIdx.x;
        int pos = FINAL_N + i;
        if (pos >= out_size) return;
        float v;
        if (i < BB*HH)                       v = g_h[i];
        else if (i < 2*BB*HH)                v = g_c[i - BB*HH];
        else if (i < 2*BB*HH + BB*HH2)       v = g_ct[i - 2*BB*HH];
        else if (i < 2*BB*HH + BB*HH2 + BB*TKK) v = g_attn[i - 2*BB*HH - BB*HH2];
        else if (i < 2*BB*HH + BB*HH2 + BB*TKK + BB) v = g_pgen[i - 2*BB*HH - BB*HH2 - BB*TKK];
        else                                 v = cov_in[i - 2*BB*HH - BB*HH2 - BB*TKK - BB];
        out[pos] = v;
    }
}

// ---------------- K10: scatter-add pointer distribution ----------------
__global__ void k_scatter(float* __restrict__ out, const int* __restrict__ iev) {
    int i = blockIdx.x * 256 + threadIdx.x;
    int b = i & 63, t = i >> 6;
    int idx = iev[t * BB + b];
    float w = (1.f - g_pgen[b]) * g_attn[b * TKK + t];
    atomicAdd(out + (size_t)b * VXX + idx, w);
}

extern "C" void kernel_launch(void* const* d_in, const int* in_sizes, int n_in,
                              void* d_out, int out_size) {
    const int*   ids   = (const int*)  d_in[0];
    const float* h0    = (const float*)d_in[1];
    const float* c0    = (const float*)d_in[2];
    const float* eo    = (const float*)d_in[3];
    const float* ef    = (const float*)d_in[4];
    const float* mask  = (const float*)d_in[5];
    const float* ct1   = (const float*)d_in[6];
    const int*   iev   = (const int*)  d_in[7];
    const float* cov   = (const float*)d_in[8];
    const float* W_emb = (const float*)d_in[10];
    const float* W_ctx = (const float*)d_in[11];
    const float* b_ctx = (const float*)d_in[12];
    const float* W_ih  = (const float*)d_in[13];
    const float* W_hh  = (const float*)d_in[14];
    const float* b_ih  = (const float*)d_in[15];
    const float* b_hh  = (const float*)d_in[16];
    const float* W_attn= (const float*)d_in[17];
    const float* b_attn= (const float*)d_in[18];
    const float* v_attn= (const float*)d_in[19];
    const float* W_pgen= (const float*)d_in[20];
    const float* b_pgen= (const float*)d_in[21];
    const float* W_out1= (const float*)d_in[22];
    const float* b_out1= (const float*)d_in[23];
    const float* W_out2= (const float*)d_in[24];
    const float* b_out2= (const float*)d_in[25];
    float* out = (float*)d_out;

    k_x<<<128, 256>>>(ids, ct1, W_emb, W_ctx, b_ctx);
    k_lstm<<<128, 256>>>(h0, c0, W_ih, W_hh, b_ih, b_hh);
    k_attnfeat<<<256, 256>>>(W_attn, b_attn);
    // PROBE (4th launch = ncu capture slot): duplicate k_logits on current g_out1.
    // Its g_logits output is fully overwritten by the real k_logits below, so the
    // final output is unchanged; total-time delta vs R12 measures T_logits.
    k_logits<<<(VV + 127) / 128, 256>>>(W_out2, b_out2);
    k_scores<<<1024, 256>>>(reinterpret_cast<const float4*>(ef), v_attn);
    k_ct<<<512, 256>>>(reinterpret_cast<const float4*>(eo), mask);
    k_out1<<<129, 256>>>(W_out1, b_out1, W_pgen, b_pgen);
    k_logits<<<(VV + 127) / 128, 256>>>(W_out2, b_out2);
    k_vstats1<<<256, 256>>>();
    k_vstats2<<<64, 32>>>();
    int tail_blocks = (out_size > FINAL_N) ? (out_size - FINAL_N + 255) / 256 : 0;
    k_final<<<FINAL_BLOCKS + tail_blocks, 256>>>(out, cov, out_size);
    k_scatter<<<(BB * TKK) / 256, 256>>>(out, iev);
}

// round 15
// speedup vs baseline: 1.0920x; 1.0920x over previous
#include <cuda_runtime.h>
#include <cuda_bf16.h>
#include <cstdint>
#include <cstddef>

#define BB    64
#define TKK   2048
#define HH    512
#define HH2   1024
#define EE    128
#define KCTX  1152      // 2H + E
#define VV    50000
#define VXX   50512     // V + NOOV
#define FINAL_N  (BB*VXX)
#define FINAL_BLOCKS (64*198)

// ---------------- scratch ----------------
__device__ __align__(16) float g_x[BB*EE];
__device__ __align__(16) float g_h[BB*HH];
__device__ __align__(16) float g_c[BB*HH];
__device__ __align__(16) float g_hc[BB*HH2];
__device__ __align__(16) float g_df[BB*HH2];
__device__ __align__(16) float g_scores[BB*TKK];
__device__ __align__(16) float g_attn[BB*TKK];
__device__ __align__(16) float g_ct[BB*HH2];
__device__ __align__(16) float g_out1[BB*HH];
__device__ float g_pgen[BB];
__device__ float g_scale[BB];
__device__ float g_vmax[BB];
__device__ float g_pm[256];
__device__ float g_ps[256];
__device__ __align__(16) float g_logits[BB*VV];

// ---------------- helpers ----------------
__device__ __forceinline__ float warpSum(float v) {
#pragma unroll
    for (int o = 16; o; o >>= 1) v += __shfl_xor_sync(0xffffffffu, v, o);
    return v;
}
__device__ __forceinline__ float warpMax(float v) {
#pragma unroll
    for (int o = 16; o; o >>= 1) v = fmaxf(v, __shfl_xor_sync(0xffffffffu, v, o));
    return v;
}
__device__ __forceinline__ float sigm(float x) { return 1.f / (1.f + __expf(-x)); }
__device__ __forceinline__ float htanh(float x) {
    float y;
    asm("tanh.approx.f32 %0, %1;" : "=f"(y) : "f"(x));
    return y;
}
__device__ __forceinline__ unsigned long long rep2(float v) {
    unsigned long long r;
    asm("mov.b64 %0, {%1,%1};" : "=l"(r) : "f"(v));
    return r;
}
__device__ __forceinline__ void fma2(unsigned long long& d, unsigned long long a, unsigned long long b) {
    asm("fma.rn.f32x2 %0, %1, %2, %0;" : "+l"(d) : "l"(a), "l"(b));
}
__device__ __forceinline__ void unpack2(unsigned long long p, float& lo, float& hi) {
    asm("mov.b64 {%0,%1}, %2;" : "=f"(lo), "=f"(hi) : "l"(p));
}

// ---------------- K1: x = concat(c_t_1, emb) @ W_ctx^T + b_ctx  [64,128] ----------------
// block = b; concat staged in smem coalesced; W_ctx rows streamed coalesced.
__global__ void __launch_bounds__(256) k_x(const int* __restrict__ ids, const float* __restrict__ ct1,
                    const float* __restrict__ W_emb, const float* __restrict__ W_ctx,
                    const float* __restrict__ b_ctx) {
    __shared__ float xv[KCTX];
    int b = blockIdx.x, tid = threadIdx.x;
    // ct1 part: 1024 floats, 256 threads x float4
    reinterpret_cast<float4*>(xv)[tid] = reinterpret_cast<const float4*>(ct1 + b * HH2)[tid];
    // emb part: 128 floats
    if (tid < 32) {
        int id = ids[b];
        reinterpret_cast<float4*>(xv + HH2)[tid] =
            reinterpret_cast<const float4*>(W_emb + (size_t)id * EE)[tid];
    }
    __syncthreads();
    int warp = tid >> 5, lane = tid & 31;
#pragma unroll 1
    for (int eo = 0; eo < 16; eo++) {
        int e = warp * 16 + eo;
        const float* w = W_ctx + (size_t)e * KCTX;
        float acc = 0.f;
#pragma unroll 4
        for (int k = lane; k < KCTX; k += 32) acc += xv[k] * w[k];
        acc = warpSum(acc);
        if (lane == 0) g_x[b * EE + e] = acc + b_ctx[e];
    }
}

// ---------------- K2: LSTM ----------------
__global__ void k_lstm(const float* __restrict__ h0, const float* __restrict__ c0,
                       const float* __restrict__ W_ih, const float* __restrict__ W_hh,
                       const float* __restrict__ b_ih, const float* __restrict__ b_hh) {
    __shared__ float s[64 * 129];
    int tid = threadIdx.x;
    int b = tid & 63, ty = tid >> 6;
    int j = blockIdx.x * 4 + ty;
    float ai = 0.f, af = 0.f, ag = 0.f, ao = 0.f;

    for (int i = tid; i < 64 * 128; i += 256) { int r = i >> 7, c = i & 127; s[r * 129 + c] = g_x[i]; }
    __syncthreads();
    {
        const float* wi = W_ih + (size_t)j * EE;
#pragma unroll 4
        for (int k = 0; k < EE; k++) {
            float xvv = s[b * 129 + k];
            ai += xvv * wi[k];
            af += xvv * wi[(size_t)HH * EE + k];
            ag += xvv * wi[(size_t)2 * HH * EE + k];
            ao += xvv * wi[(size_t)3 * HH * EE + k];
        }
    }
    for (int kt = 0; kt < 4; kt++) {
        __syncthreads();
        for (int i = tid; i < 64 * 128; i += 256) {
            int r = i >> 7, c = i & 127;
            s[r * 129 + c] = h0[r * HH + kt * 128 + c];
        }
        __syncthreads();
        const float* wh = W_hh + (size_t)j * HH + kt * 128;
#pragma unroll 4
        for (int k = 0; k < 128; k++) {
            float hv = s[b * 129 + k];
            ai += hv * wh[k];
            af += hv * wh[(size_t)HH * HH + k];
            ag += hv * wh[(size_t)2 * HH * HH + k];
            ao += hv * wh[(size_t)3 * HH * HH + k];
        }
    }
    ai += b_ih[j]          + b_hh[j];
    af += b_ih[HH + j]     + b_hh[HH + j];
    ag += b_ih[2 * HH + j] + b_hh[2 * HH + j];
    ao += b_ih[3 * HH + j] + b_hh[3 * HH + j];

    float cprev = c0[b * HH + j];
    float cc = sigm(af) * cprev + sigm(ai) * tanhf(ag);
    float hh = sigm(ao) * tanhf(cc);
    g_c[b * HH + j] = cc;
    g_h[b * HH + j] = hh;
    g_hc[b * HH2 + j] = hh;
    g_hc[b * HH2 + HH + j] = cc;
}

// ---------------- K3: dec_feature (+ zero g_ct) ----------------
__global__ void k_attnfeat(const float* __restrict__ W_attn, const float* __restrict__ b_attn) {
    __shared__ float s[64 * 129];
    int tid = threadIdx.x;
    g_ct[blockIdx.x * 256 + tid] = 0.f;
    int b = tid & 63, ty = tid >> 6;
    int n = blockIdx.x * 4 + ty;
    float acc = 0.f;
    const float* w = W_attn + (size_t)n * HH2;
    for (int kt = 0; kt < 8; kt++) {
        __syncthreads();
        for (int i = tid; i < 64 * 128; i += 256) {
            int r = i >> 7, c = i & 127;
            s[r * 129 + c] = g_hc[r * HH2 + kt * 128 + c];
        }
        __syncthreads();
#pragma unroll 4
        for (int k = 0; k < 128; k++) acc += s[b * 129 + k] * w[kt * 128 + k];
    }
    g_df[b * HH2 + n] = acc + b_attn[n];
}

// ---------------- K4: scores (512MB stream), R12-proven ----------------
__global__ void __launch_bounds__(256) k_scores(const float4* __restrict__ ef4,
                                                const float* __restrict__ vat) {
    __shared__ float4 sdf[256];
    __shared__ float4 svv[256];
    int bb = blockIdx.x >> 4;
    int tc = blockIdx.x & 15;
    int tid = threadIdx.x;
    sdf[tid] = reinterpret_cast<const float4*>(g_df + bb * HH2)[tid];
    svv[tid] = reinterpret_cast<const float4*>(vat)[tid];
    __syncthreads();
    int warp = tid >> 5, lane = tid & 31;
    for (int r = 0; r < 16; r++) {
        int t = tc * 128 + warp * 16 + r;
        const float4* er = ef4 + ((size_t)(bb * TKK + t)) * 256;
        float acc = 0.f;
#pragma unroll
        for (int i = 0; i < 8; i++) {
            float4 e = er[i * 32 + lane];
            float4 d = sdf[i * 32 + lane];
            float4 v = svv[i * 32 + lane];
            acc += v.x * htanh(e.x + d.x);
            acc += v.y * htanh(e.y + d.y);
            acc += v.z * htanh(e.z + d.z);
            acc += v.w * htanh(e.w + d.w);
        }
        float s = warpSum(acc);
        if (lane == 0) g_scores[bb * TKK + t] = s;
    }
}

// ---------------- K5: c_t (512MB stream) with fused attention softmax ----------------
__global__ void __launch_bounds__(256) k_ct(const float4* __restrict__ eo4,
                                            const float* __restrict__ mask) {
    __shared__ float as[256];
    __shared__ float red[8];
    int b = blockIdx.x >> 3, tc = blockIdx.x & 7;
    int tid = threadIdx.x;
    int warp = tid >> 5, lane = tid & 31;
    const float* sc = g_scores + b * TKK;
    const float* mk = mask + b * TKK;

    float m = -3.4e38f;
    for (int t = tid; t < TKK; t += 256) m = fmaxf(m, sc[t]);
    m = warpMax(m);
    if (lane == 0) red[warp] = m;
    __syncthreads();
    float mm = red[0];
#pragma unroll
    for (int i = 1; i < 8; i++) mm = fmaxf(mm, red[i]);
    __syncthreads();
    float s = 0.f;
    for (int t = tid; t < TKK; t += 256) s += __expf(sc[t] - mm) * mk[t];
    s = warpSum(s);
    if (lane == 0) red[warp] = s;
    __syncthreads();
    float tot = 0.f;
#pragma unroll
    for (int i = 0; i < 8; i++) tot += red[i];
    float inv = 1.f / tot;

    int t0 = tc * 256;
    float av = __expf(sc[t0 + tid] - mm) * mk[t0 + tid] * inv;
    g_attn[b * TKK + t0 + tid] = av;
    as[tid] = av;
    __syncthreads();

    const float4* base = eo4 + ((size_t)(b * TKK + t0)) * 256 + tid;
    float4 a0 = make_float4(0.f,0.f,0.f,0.f), a1 = a0, a2 = a0, a3 = a0;
#pragma unroll 2
    for (int t = 0; t < 256; t += 4) {
        float4 e0 = base[(size_t)(t + 0) * 256];
        float4 e1 = base[(size_t)(t + 1) * 256];
        float4 e2 = base[(size_t)(t + 2) * 256];
        float4 e3 = base[(size_t)(t + 3) * 256];
        float w0 = as[t], w1 = as[t+1], w2 = as[t+2], w3 = as[t+3];
        a0.x += w0*e0.x; a0.y += w0*e0.y; a0.z += w0*e0.z; a0.w += w0*e0.w;
        a1.x += w1*e1.x; a1.y += w1*e1.y; a1.z += w1*e1.z; a1.w += w1*e1.w;
        a2.x += w2*e2.x; a2.y += w2*e2.y; a2.z += w2*e2.z; a2.w += w2*e2.w;
        a3.x += w3*e3.x; a3.y += w3*e3.y; a3.z += w3*e3.z; a3.w += w3*e3.w;
    }
    float* dst = g_ct + b * HH2 + tid * 4;
    atomicAdd(dst + 0, a0.x + a1.x + a2.x + a3.x);
    atomicAdd(dst + 1, a0.y + a1.y + a2.y + a3.y);
    atomicAdd(dst + 2, a0.z + a1.z + a2.z + a3.z);
    atomicAdd(dst + 3, a0.w + a1.w + a2.w + a3.w);
}

// ---------------- K6: out1 + p_gen ----------------
__global__ void k_out1(const float* __restrict__ W1, const float* __restrict__ b1,
                       const float* __restrict__ Wp, const float* __restrict__ bp) {
    __shared__ float s[64 * 129];
    int tid = threadIdx.x;
    if (blockIdx.x < 128) {
        int b = tid & 63, ty = tid >> 6;
        int m = blockIdx.x * 4 + ty;
        float acc = 0.f;
        const float* w = W1 + (size_t)m * 1536;
        for (int kt = 0; kt < 12; kt++) {
            __syncthreads();
            for (int i = tid; i < 64 * 128; i += 256) {
                int r = i >> 7, c = i & 127;
                int kk = kt * 128 + c;
                s[r * 129 + c] = (kk < HH) ? g_h[r * HH + kk] : g_ct[r * HH2 + kk - HH];
            }
            __syncthreads();
#pragma unroll 4
            for (int k = 0; k < 128; k++) acc += s[b * 129 + k] * w[kt * 128 + k];
        }
        g_out1[b * HH + m] = acc + b1[m];
    } else {
        int warp = tid >> 5, lane = tid & 31;
        for (int b = warp; b < BB; b += 8) {
            float acc = 0.f;
            for (int k = lane; k < 2176; k += 32) {
                float pv;
                if (k < HH2)       pv = g_ct[b * HH2 + k];
                else if (k < 2048) pv = g_hc[b * HH2 + (k - HH2)];
                else               pv = g_x[b * EE + (k - 2048)];
                acc += pv * Wp[k];
            }
            acc = warpSum(acc);
            if (lane == 0) g_pgen[b] = sigm(acc + bp[0]);
        }
    }
}

// ---------------- K7: logits [64, 50000], register-staged double buffering ----------------
__global__ void __launch_bounds__(256) k_logits(const float* __restrict__ W2,
                                                const float* __restrict__ b2) {
    __shared__ float s_x[64][72];     // [k][b]
    __shared__ float s_w[64][132];    // [k][v^swz(k)], swz=((k>>2)&7)<<2
    int tid = threadIdx.x;
    int warp = tid >> 5, lane = tid & 31;
    int v0 = blockIdx.x * 128;
    int half = lane >> 4, li = lane & 15;
    int r = tid & 63, mg = tid >> 6;

    unsigned long long acc[4][4];
#pragma unroll
    for (int ip = 0; ip < 4; ip++)
#pragma unroll
        for (int j = 0; j < 4; j++) acc[ip][j] = 0ull;

    float4 xreg[4], wreg[8];
    // stage tile 0
#pragma unroll
    for (int it = 0; it < 4; it++)
        xreg[it] = *reinterpret_cast<const float4*>(g_out1 + r * HH + mg * 16 + it * 4);
#pragma unroll
    for (int it = 0; it < 8; it++) {
        int vg = v0 + it * 16 + warp * 2 + half;
        wreg[it] = (vg < VV) ? *reinterpret_cast<const float4*>(W2 + (size_t)vg * HH + 4 * li)
                             : make_float4(0.f, 0.f, 0.f, 0.f);
    }

    for (int t = 0; t < 8; t++) {
        __syncthreads();           // prior tile's compute done
        // stores: regs -> smem (swizzled)
#pragma unroll
        for (int it = 0; it < 4; it++) {
            int c = mg * 16 + it * 4;
            s_x[c + 0][r] = xreg[it].x; s_x[c + 1][r] = xreg[it].y;
            s_x[c + 2][r] = xreg[it].z; s_x[c + 3][r] = xreg[it].w;
        }
#pragma unroll
        for (int it = 0; it < 8; it++) {
            int row = it * 16 + warp * 2 + half;
            int sw = row ^ ((li & 7) << 2);
            s_w[4 * li + 0][sw] = wreg[it].x; s_w[4 * li + 1][sw] = wreg[it].y;
            s_w[4 * li + 2][sw] = wreg[it].z; s_w[4 * li + 3][sw] = wreg[it].w;
        }
        __syncthreads();           // tile visible
        // prefetch next tile (LDGs in flight during compute below)
        if (t < 7) {
            int k0 = (t + 1) * 64;
#pragma unroll
            for (int it = 0; it < 4; it++)
                xreg[it] = *reinterpret_cast<const float4*>(g_out1 + r * HH + k0 + mg * 16 + it * 4);
#pragma unroll
            for (int it = 0; it < 8; it++) {
                int vg = v0 + it * 16 + warp * 2 + half;
                wreg[it] = (vg < VV) ? *reinterpret_cast<const float4*>(W2 + (size_t)vg * HH + k0 + 4 * li)
                                     : make_float4(0.f, 0.f, 0.f, 0.f);
            }
        }
        // compute on current tile
#pragma unroll 8
        for (int k = 0; k < 64; k++) {
            int swz = ((k >> 2) & 7) << 2;
            float4 w4 = *reinterpret_cast<const float4*>(&s_w[k][(4 * lane) ^ swz]);
            ulonglong2 xa = *reinterpret_cast<const ulonglong2*>(&s_x[k][warp * 8]);
            ulonglong2 xb = *reinterpret_cast<const ulonglong2*>(&s_x[k][warp * 8 + 4]);
            unsigned long long w0 = rep2(w4.x), w1 = rep2(w4.y), w2 = rep2(w4.z), w3 = rep2(w4.w);
            fma2(acc[0][0], xa.x, w0); fma2(acc[0][1], xa.x, w1); fma2(acc[0][2], xa.x, w2); fma2(acc[0][3], xa.x, w3);
            fma2(acc[1][0], xa.y, w0); fma2(acc[1][1], xa.y, w1); fma2(acc[1][2], xa.y, w2); fma2(acc[1][3], xa.y, w3);
            fma2(acc[2][0], xb.x, w0); fma2(acc[2][1], xb.x, w1); fma2(acc[2][2], xb.x, w2); fma2(acc[2][3], xb.x, w3);
            fma2(acc[3][0], xb.y, w0); fma2(acc[3][1], xb.y, w1); fma2(acc[3][2], xb.y, w2); fma2(acc[3][3], xb.y, w3);
        }
    }
    int v = v0 + 4 * lane;
    if (v < VV) {
        float4 bias = *reinterpret_cast<const float4*>(b2 + v);
#pragma unroll
        for (int ip = 0; ip < 4; ip++) {
            float lo0, hi0, lo1, hi1, lo2, hi2, lo3, hi3;
            unpack2(acc[ip][0], lo0, hi0); unpack2(acc[ip][1], lo1, hi1);
            unpack2(acc[ip][2], lo2, hi2); unpack2(acc[ip][3], lo3, hi3);
            int b = warp * 8 + 2 * ip;
            float4 r0 = make_float4(lo0 + bias.x, lo1 + bias.y, lo2 + bias.z, lo3 + bias.w);
            float4 r1 = make_float4(hi0 + bias.x, hi1 + bias.y, hi2 + bias.z, hi3 + bias.w);
            *reinterpret_cast<float4*>(g_logits + (size_t)b * VV + v)       = r0;
            *reinterpret_cast<float4*>(g_logits + (size_t)(b + 1) * VV + v) = r1;
        }
    }
}

// ---------------- K8a: partial vocab softmax stats ----------------
__global__ void k_vstats1() {
    __shared__ float sh[8];
    int b = blockIdx.x >> 2, q = blockIdx.x & 3;
    int tid = threadIdx.x, warp = tid >> 5, lane = tid & 31;
    const float* lg = g_logits + (size_t)b * VV;
    int lo = q * 12500, hi = lo + 12500;
    float m = -3.4e38f;
    for (int v = lo + tid; v < hi; v += 256) m = fmaxf(m, lg[v]);
    m = warpMax(m);
    if (lane == 0) sh[warp] = m;
    __syncthreads();
    float mm = sh[0];
#pragma unroll
    for (int i = 1; i < 8; i++) mm = fmaxf(mm, sh[i]);
    __syncthreads();
    float s = 0.f;
    for (int v = lo + tid; v < hi; v += 256) s += __expf(lg[v] - mm);
    s = warpSum(s);
    if (lane == 0) sh[warp] = s;
    __syncthreads();
    if (tid == 0) {
        float tot = 0.f;
#pragma unroll
        for (int i = 0; i < 8; i++) tot += sh[i];
        g_pm[blockIdx.x] = mm;
        g_ps[blockIdx.x] = tot;
    }
}

// ---------------- K8b: combine partials ----------------
__global__ void k_vstats2() {
    int b = blockIdx.x, lane = threadIdx.x;
    float pm = (lane < 4) ? g_pm[b * 4 + lane] : -3.4e38f;
    float mm = warpMax(pm);
    float ps = (lane < 4) ? g_ps[b * 4 + lane] * __expf(pm - mm) : 0.f;
    float tot = warpSum(ps);
    if (lane == 0) { g_vmax[b] = mm; g_scale[b] = g_pgen[b] / tot; }
}

// ---------------- K9: final vocab part + tail (merged) ----------------
__global__ void __launch_bounds__(256) k_final(float* __restrict__ out,
                                               const float* __restrict__ cov_in,
                                               int out_size) {
    int bid = blockIdx.x;
    if (bid < FINAL_BLOCKS) {
        int b = bid / 198;
        int v = (bid % 198) * 256 + threadIdx.x;
        if (v >= VXX) return;
        float val = 0.f;
        if (v < VV) val = __expf(g_logits[(size_t)b * VV + v] - g_vmax[b]) * g_scale[b];
        out[(size_t)b * VXX + v] = val;
    } else {
        int i = (bid - FINAL_BLOCKS) * 256 + threadIdx.x;
        int pos = FINAL_N + i;
        if (pos >= out_size) return;
        float v;
        if (i < BB*HH)                       v = g_h[i];
        else if (i < 2*BB*HH)                v = g_c[i - BB*HH];
        else if (i < 2*BB*HH + BB*HH2)       v = g_ct[i - 2*BB*HH];
        else if (i < 2*BB*HH + BB*HH2 + BB*TKK) v = g_attn[i - 2*BB*HH - BB*HH2];
        else if (i < 2*BB*HH + BB*HH2 + BB*TKK + BB) v = g_pgen[i - 2*BB*HH - BB*HH2 - BB*TKK];
        else                                 v = cov_in[i - 2*BB*HH - BB*HH2 - BB*TKK - BB];
        out[pos] = v;
    }
}

// ---------------- K10: scatter-add pointer distribution ----------------
__global__ void k_scatter(float* __restrict__ out, const int* __restrict__ iev) {
    int i = blockIdx.x * 256 + threadIdx.x;
    int b = i & 63, t = i >> 6;
    int idx = iev[t * BB + b];
    float w = (1.f - g_pgen[b]) * g_attn[b * TKK + t];
    atomicAdd(out + (size_t)b * VXX + idx, w);
}

extern "C" void kernel_launch(void* const* d_in, const int* in_sizes, int n_in,
                              void* d_out, int out_size) {
    const int*   ids   = (const int*)  d_in[0];
    const float* h0    = (const float*)d_in[1];
    const float* c0    = (const float*)d_in[2];
    const float* eo    = (const float*)d_in[3];
    const float* ef    = (const float*)d_in[4];
    const float* mask  = (const float*)d_in[5];
    const float* ct1   = (const float*)d_in[6];
    const int*   iev   = (const int*)  d_in[7];
    const float* cov   = (const float*)d_in[8];
    const float* W_emb = (const float*)d_in[10];
    const float* W_ctx = (const float*)d_in[11];
    const float* b_ctx = (const float*)d_in[12];
    const float* W_ih  = (const float*)d_in[13];
    const float* W_hh  = (const float*)d_in[14];
    const float* b_ih  = (const float*)d_in[15];
    const float* b_hh  = (const float*)d_in[16];
    const float* W_attn= (const float*)d_in[17];
    const float* b_attn= (const float*)d_in[18];
    const float* v_attn= (const float*)d_in[19];
    const float* W_pgen= (const float*)d_in[20];
    const float* b_pgen= (const float*)d_in[21];
    const float* W_out1= (const float*)d_in[22];
    const float* b_out1= (const float*)d_in[23];
    const float* W_out2= (const float*)d_in[24];
    const float* b_out2= (const float*)d_in[25];
    float* out = (float*)d_out;

    k_x<<<64, 256>>>(ids, ct1, W_emb, W_ctx, b_ctx);
    k_lstm<<<128, 256>>>(h0, c0, W_ih, W_hh, b_ih, b_hh);
    k_attnfeat<<<256, 256>>>(W_attn, b_attn);
    k_scores<<<1024, 256>>>(reinterpret_cast<const float4*>(ef), v_attn);
    k_ct<<<512, 256>>>(reinterpret_cast<const float4*>(eo), mask);
    k_out1<<<129, 256>>>(W_out1, b_out1, W_pgen, b_pgen);
    k_logits<<<(VV + 127) / 128, 256>>>(W_out2, b_out2);
    k_vstats1<<<256, 256>>>();
    k_vstats2<<<64, 32>>>();
    int tail_blocks = (out_size > FINAL_N) ? (out_size - FINAL_N + 255) / 256 : 0;
    k_final<<<FINAL_BLOCKS + tail_blocks, 256>>>(out, cov, out_size);
    k_scatter<<<(BB * TKK) / 256, 256>>>(out, iev);
}

// round 17
// speedup vs baseline: 1.1700x; 1.0714x over previous
#include <cuda_runtime.h>
#include <cuda_bf16.h>
#include <cstdint>
#include <cstddef>

#define BB    64
#define TKK   2048
#define HH    512
#define HH2   1024
#define EE    128
#define KCTX  1152      // 2H + E
#define VV    50000
#define VXX   50512     // V + NOOV
#define FINAL_N  (BB*VXX)
#define FINAL_BLOCKS (64*198)

// ---------------- scratch ----------------
__device__ __align__(16) float g_x[BB*EE];
__device__ __align__(16) float g_h[BB*HH];
__device__ __align__(16) float g_c[BB*HH];
__device__ __align__(16) float g_hc[BB*HH2];
__device__ __align__(16) float g_df[BB*HH2];
__device__ __align__(16) float g_scores[BB*TKK];
__device__ __align__(16) float g_attn[BB*TKK];
__device__ __align__(16) float g_ct[BB*HH2];
__device__ __align__(16) float g_out1[BB*HH];
__device__ float g_pgen[BB];
__device__ float g_pm[256];
__device__ float g_ps[256];
__device__ __align__(16) float g_logits[BB*VV];

// ---------------- helpers ----------------
__device__ __forceinline__ float warpSum(float v) {
#pragma unroll
    for (int o = 16; o; o >>= 1) v += __shfl_xor_sync(0xffffffffu, v, o);
    return v;
}
__device__ __forceinline__ float warpMax(float v) {
#pragma unroll
    for (int o = 16; o; o >>= 1) v = fmaxf(v, __shfl_xor_sync(0xffffffffu, v, o));
    return v;
}
__device__ __forceinline__ float sigm(float x) { return 1.f / (1.f + __expf(-x)); }
__device__ __forceinline__ float htanh(float x) {
    float y;
    asm("tanh.approx.f32 %0, %1;" : "=f"(y) : "f"(x));
    return y;
}
__device__ __forceinline__ unsigned long long rep2(float v) {
    unsigned long long r;
    asm("mov.b64 %0, {%1,%1};" : "=l"(r) : "f"(v));
    return r;
}
__device__ __forceinline__ void fma2(unsigned long long& d, unsigned long long a, unsigned long long b) {
    asm("fma.rn.f32x2 %0, %1, %2, %0;" : "+l"(d) : "l"(a), "l"(b));
}
__device__ __forceinline__ void unpack2(unsigned long long p, float& lo, float& hi) {
    asm("mov.b64 {%0,%1}, %2;" : "=f"(lo), "=f"(hi) : "l"(p));
}

// ---------------- K1: x = concat(c_t_1, emb) @ W_ctx^T + b_ctx  [64,128] ----------------
__global__ void __launch_bounds__(256) k_x(const int* __restrict__ ids, const float* __restrict__ ct1,
                    const float* __restrict__ W_emb, const float* __restrict__ W_ctx,
                    const float* __restrict__ b_ctx) {
    __shared__ float xv[KCTX];
    int b = blockIdx.x, tid = threadIdx.x;
    reinterpret_cast<float4*>(xv)[tid] = reinterpret_cast<const float4*>(ct1 + b * HH2)[tid];
    if (tid < 32) {
        int id = ids[b];
        reinterpret_cast<float4*>(xv + HH2)[tid] =
            reinterpret_cast<const float4*>(W_emb + (size_t)id * EE)[tid];
    }
    __syncthreads();
    int warp = tid >> 5, lane = tid & 31;
#pragma unroll 1
    for (int eo = 0; eo < 16; eo++) {
        int e = warp * 16 + eo;
        const float* w = W_ctx + (size_t)e * KCTX;
        float acc = 0.f;
#pragma unroll 4
        for (int k = lane; k < KCTX; k += 32) acc += xv[k] * w[k];
        acc = warpSum(acc);
        if (lane == 0) g_x[b * EE + e] = acc + b_ctx[e];
    }
}

// ---------------- K2: LSTM, weights staged in smem ----------------
__global__ void k_lstm(const float* __restrict__ h0, const float* __restrict__ c0,
                       const float* __restrict__ W_ih, const float* __restrict__ W_hh,
                       const float* __restrict__ b_ih, const float* __restrict__ b_hh) {
    __shared__ float s[64 * 129];
    __shared__ float sw[16 * 132];    // 16 rows (4 gates x 4 units) x 128 k
    int tid = threadIdx.x;
    int b = tid & 63, ty = tid >> 6;
    int j = blockIdx.x * 4 + ty;
    float ai = 0.f, af = 0.f, ag = 0.f, ao = 0.f;

    // ---- x part ----
    for (int i = tid; i < 64 * 128; i += 256) { int r = i >> 7, c = i & 127; s[r * 129 + c] = g_x[i]; }
#pragma unroll
    for (int f = tid; f < 512; f += 256) {
        int row = f >> 5, c4 = f & 31;           // row = g*4+u
        int g = row >> 2, u = row & 3;
        float4 wv = *reinterpret_cast<const float4*>(
            W_ih + ((size_t)g * HH + blockIdx.x * 4 + u) * EE + c4 * 4);
        *reinterpret_cast<float4*>(sw + row * 132 + c4 * 4) = wv;
    }
    __syncthreads();
#pragma unroll 4
    for (int k = 0; k < EE; k++) {
        float xvv = s[b * 129 + k];
        ai += xvv * sw[(0  + ty) * 132 + k];
        af += xvv * sw[(4  + ty) * 132 + k];
        ag += xvv * sw[(8  + ty) * 132 + k];
        ao += xvv * sw[(12 + ty) * 132 + k];
    }
    // ---- h part (4 tiles of 128) ----
    for (int kt = 0; kt < 4; kt++) {
        __syncthreads();
        for (int i = tid; i < 64 * 128; i += 256) {
            int r = i >> 7, c = i & 127;
            s[r * 129 + c] = h0[r * HH + kt * 128 + c];
        }
#pragma unroll
        for (int f = tid; f < 512; f += 256) {
            int row = f >> 5, c4 = f & 31;
            int g = row >> 2, u = row & 3;
            float4 wv = *reinterpret_cast<const float4*>(
                W_hh + ((size_t)g * HH + blockIdx.x * 4 + u) * HH + kt * 128 + c4 * 4);
            *reinterpret_cast<float4*>(sw + row * 132 + c4 * 4) = wv;
        }
        __syncthreads();
#pragma unroll 4
        for (int k = 0; k < 128; k++) {
            float hv = s[b * 129 + k];
            ai += hv * sw[(0  + ty) * 132 + k];
            af += hv * sw[(4  + ty) * 132 + k];
            ag += hv * sw[(8  + ty) * 132 + k];
            ao += hv * sw[(12 + ty) * 132 + k];
        }
    }
    ai += b_ih[j]          + b_hh[j];
    af += b_ih[HH + j]     + b_hh[HH + j];
    ag += b_ih[2 * HH + j] + b_hh[2 * HH + j];
    ao += b_ih[3 * HH + j] + b_hh[3 * HH + j];

    float cprev = c0[b * HH + j];
    float cc = sigm(af) * cprev + sigm(ai) * tanhf(ag);
    float hh = sigm(ao) * tanhf(cc);
    g_c[b * HH + j] = cc;
    g_h[b * HH + j] = hh;
    g_hc[b * HH2 + j] = hh;
    g_hc[b * HH2 + HH + j] = cc;
}

// ---------------- K3: dec_feature (+ zero g_ct), weights staged ----------------
__global__ void k_attnfeat(const float* __restrict__ W_attn, const float* __restrict__ b_attn) {
    __shared__ float s[64 * 129];
    __shared__ float sw[4 * 132];
    int tid = threadIdx.x;
    g_ct[blockIdx.x * 256 + tid] = 0.f;
    int b = tid & 63, ty = tid >> 6;
    int n = blockIdx.x * 4 + ty;
    float acc = 0.f;
    for (int kt = 0; kt < 8; kt++) {
        __syncthreads();
        for (int i = tid; i < 64 * 128; i += 256) {
            int r = i >> 7, c = i & 127;
            s[r * 129 + c] = g_hc[r * HH2 + kt * 128 + c];
        }
        if (tid < 128) {
            int row = tid >> 5, c4 = tid & 31;
            float4 wv = *reinterpret_cast<const float4*>(
                W_attn + (size_t)(blockIdx.x * 4 + row) * HH2 + kt * 128 + c4 * 4);
            *reinterpret_cast<float4*>(sw + row * 132 + c4 * 4) = wv;
        }
        __syncthreads();
#pragma unroll 4
        for (int k = 0; k < 128; k++) acc += s[b * 129 + k] * sw[ty * 132 + k];
    }
    g_df[b * HH2 + n] = acc + b_attn[n];
}

// ---------------- K4: scores (512MB stream), R12-proven ----------------
__global__ void __launch_bounds__(256) k_scores(const float4* __restrict__ ef4,
                                                const float* __restrict__ vat) {
    __shared__ float4 sdf[256];
    __shared__ float4 svv[256];
    int bb = blockIdx.x >> 4;
    int tc = blockIdx.x & 15;
    int tid = threadIdx.x;
    sdf[tid] = reinterpret_cast<const float4*>(g_df + bb * HH2)[tid];
    svv[tid] = reinterpret_cast<const float4*>(vat)[tid];
    __syncthreads();
    int warp = tid >> 5, lane = tid & 31;
    for (int r = 0; r < 16; r++) {
        int t = tc * 128 + warp * 16 + r;
        const float4* er = ef4 + ((size_t)(bb * TKK + t)) * 256;
        float acc = 0.f;
#pragma unroll
        for (int i = 0; i < 8; i++) {
            float4 e = er[i * 32 + lane];
            float4 d = sdf[i * 32 + lane];
            float4 v = svv[i * 32 + lane];
            acc += v.x * htanh(e.x + d.x);
            acc += v.y * htanh(e.y + d.y);
            acc += v.z * htanh(e.z + d.z);
            acc += v.w * htanh(e.w + d.w);
        }
        float s = warpSum(acc);
        if (lane == 0) g_scores[bb * TKK + t] = s;
    }
}

// ---------------- K5: c_t (512MB stream) with fused attention softmax ----------------
__global__ void __launch_bounds__(256) k_ct(const float4* __restrict__ eo4,
                                            const float* __restrict__ mask) {
    __shared__ float as[256];
    __shared__ float red[8];
    int b = blockIdx.x >> 3, tc = blockIdx.x & 7;
    int tid = threadIdx.x;
    int warp = tid >> 5, lane = tid & 31;
    const float* sc = g_scores + b * TKK;
    const float* mk = mask + b * TKK;

    float m = -3.4e38f;
    for (int t = tid; t < TKK; t += 256) m = fmaxf(m, sc[t]);
    m = warpMax(m);
    if (lane == 0) red[warp] = m;
    __syncthreads();
    float mm = red[0];
#pragma unroll
    for (int i = 1; i < 8; i++) mm = fmaxf(mm, red[i]);
    __syncthreads();
    float s = 0.f;
    for (int t = tid; t < TKK; t += 256) s += __expf(sc[t] - mm) * mk[t];
    s = warpSum(s);
    if (lane == 0) red[warp] = s;
    __syncthreads();
    float tot = 0.f;
#pragma unroll
    for (int i = 0; i < 8; i++) tot += red[i];
    float inv = 1.f / tot;

    int t0 = tc * 256;
    float av = __expf(sc[t0 + tid] - mm) * mk[t0 + tid] * inv;
    g_attn[b * TKK + t0 + tid] = av;
    as[tid] = av;
    __syncthreads();

    const float4* base = eo4 + ((size_t)(b * TKK + t0)) * 256 + tid;
    float4 a0 = make_float4(0.f,0.f,0.f,0.f), a1 = a0, a2 = a0, a3 = a0;
#pragma unroll 2
    for (int t = 0; t < 256; t += 4) {
        float4 e0 = base[(size_t)(t + 0) * 256];
        float4 e1 = base[(size_t)(t + 1) * 256];
        float4 e2 = base[(size_t)(t + 2) * 256];
        float4 e3 = base[(size_t)(t + 3) * 256];
        float w0 = as[t], w1 = as[t+1], w2 = as[t+2], w3 = as[t+3];
        a0.x += w0*e0.x; a0.y += w0*e0.y; a0.z += w0*e0.z; a0.w += w0*e0.w;
        a1.x += w1*e1.x; a1.y += w1*e1.y; a1.z += w1*e1.z; a1.w += w1*e1.w;
        a2.x += w2*e2.x; a2.y += w2*e2.y; a2.z += w2*e2.z; a2.w += w2*e2.w;
        a3.x += w3*e3.x; a3.y += w3*e3.y; a3.z += w3*e3.z; a3.w += w3*e3.w;
    }
    float* dst = g_ct + b * HH2 + tid * 4;
    atomicAdd(dst + 0, a0.x + a1.x + a2.x + a3.x);
    atomicAdd(dst + 1, a0.y + a1.y + a2.y + a3.y);
    atomicAdd(dst + 2, a0.z + a1.z + a2.z + a3.z);
    atomicAdd(dst + 3, a0.w + a1.w + a2.w + a3.w);
}

// ---------------- K6: out1 + p_gen, weights staged ----------------
__global__ void k_out1(const float* __restrict__ W1, const float* __restrict__ b1,
                       const float* __restrict__ Wp, const float* __restrict__ bp) {
    __shared__ float s[64 * 129];
    __shared__ float sw[4 * 132];
    int tid = threadIdx.x;
    if (blockIdx.x < 128) {
        int b = tid & 63, ty = tid >> 6;
        int m = blockIdx.x * 4 + ty;
        float acc = 0.f;
        for (int kt = 0; kt < 12; kt++) {
            __syncthreads();
            for (int i = tid; i < 64 * 128; i += 256) {
                int r = i >> 7, c = i & 127;
                int kk = kt * 128 + c;
                s[r * 129 + c] = (kk < HH) ? g_h[r * HH + kk] : g_ct[r * HH2 + kk - HH];
            }
            if (tid < 128) {
                int row = tid >> 5, c4 = tid & 31;
                float4 wv = *reinterpret_cast<const float4*>(
                    W1 + (size_t)(blockIdx.x * 4 + row) * 1536 + kt * 128 + c4 * 4);
                *reinterpret_cast<float4*>(sw + row * 132 + c4 * 4) = wv;
            }
            __syncthreads();
#pragma unroll 4
            for (int k = 0; k < 128; k++) acc += s[b * 129 + k] * sw[ty * 132 + k];
        }
        g_out1[b * HH + m] = acc + b1[m];
    } else {
        int warp = tid >> 5, lane = tid & 31;
        for (int b = warp; b < BB; b += 8) {
            float acc = 0.f;
            for (int k = lane; k < 2176; k += 32) {
                float pv;
                if (k < HH2)       pv = g_ct[b * HH2 + k];
                else if (k < 2048) pv = g_hc[b * HH2 + (k - HH2)];
                else               pv = g_x[b * EE + (k - 2048)];
                acc += pv * Wp[k];
            }
            acc = warpSum(acc);
            if (lane == 0) g_pgen[b] = sigm(acc + bp[0]);
        }
    }
}

// ---------------- K7: logits [64, 50000] (R12-proven version) ----------------
__global__ void __launch_bounds__(256) k_logits(const float* __restrict__ W2,
                                                const float* __restrict__ b2) {
    __shared__ float s_x[64][72];     // [k][b]
    __shared__ float s_w[64][132];    // [k][v^swz(k)], swz=((k>>2)&7)<<2
    int tid = threadIdx.x;
    int warp = tid >> 5, lane = tid & 31;
    int v0 = blockIdx.x * 128;
    int half = lane >> 4, li = lane & 15;

    unsigned long long acc[4][4];
#pragma unroll
    for (int ip = 0; ip < 4; ip++)
#pragma unroll
        for (int j = 0; j < 4; j++) acc[ip][j] = 0ull;

    for (int k0 = 0; k0 < HH; k0 += 64) {
        __syncthreads();
        {
            int r = tid & 63, m = tid >> 6;
#pragma unroll
            for (int it = 0; it < 4; it++) {
                int c = m * 16 + it * 4;
                float4 xv = *reinterpret_cast<const float4*>(g_out1 + r * HH + k0 + c);
                s_x[c + 0][r] = xv.x; s_x[c + 1][r] = xv.y;
                s_x[c + 2][r] = xv.z; s_x[c + 3][r] = xv.w;
            }
        }
#pragma unroll
        for (int it = 0; it < 8; it++) {
            int row = it * 16 + warp * 2 + half;
            int vg = v0 + row;
            float4 wv = make_float4(0.f, 0.f, 0.f, 0.f);
            if (vg < VV) wv = *reinterpret_cast<const float4*>(W2 + (size_t)vg * HH + k0 + 4 * li);
            int sw = row ^ ((li & 7) << 2);
            s_w[4 * li + 0][sw] = wv.x; s_w[4 * li + 1][sw] = wv.y;
            s_w[4 * li + 2][sw] = wv.z; s_w[4 * li + 3][sw] = wv.w;
        }
        __syncthreads();
#pragma unroll 8
        for (int k = 0; k < 64; k++) {
            int swz = ((k >> 2) & 7) << 2;
            float4 w4 = *reinterpret_cast<const float4*>(&s_w[k][(4 * lane) ^ swz]);
            ulonglong2 xa = *reinterpret_cast<const ulonglong2*>(&s_x[k][warp * 8]);
            ulonglong2 xb = *reinterpret_cast<const ulonglong2*>(&s_x[k][warp * 8 + 4]);
            unsigned long long w0 = rep2(w4.x), w1 = rep2(w4.y), w2 = rep2(w4.z), w3 = rep2(w4.w);
            fma2(acc[0][0], xa.x, w0); fma2(acc[0][1], xa.x, w1); fma2(acc[0][2], xa.x, w2); fma2(acc[0][3], xa.x, w3);
            fma2(acc[1][0], xa.y, w0); fma2(acc[1][1], xa.y, w1); fma2(acc[1][2], xa.y, w2); fma2(acc[1][3], xa.y, w3);
            fma2(acc[2][0], xb.x, w0); fma2(acc[2][1], xb.x, w1); fma2(acc[2][2], xb.x, w2); fma2(acc[2][3], xb.x, w3);
            fma2(acc[3][0], xb.y, w0); fma2(acc[3][1], xb.y, w1); fma2(acc[3][2], xb.y, w2); fma2(acc[3][3], xb.y, w3);
        }
    }
    int v = v0 + 4 * lane;
    if (v < VV) {
        float4 bias = *reinterpret_cast<const float4*>(b2 + v);
#pragma unroll
        for (int ip = 0; ip < 4; ip++) {
            float lo0, hi0, lo1, hi1, lo2, hi2, lo3, hi3;
            unpack2(acc[ip][0], lo0, hi0); unpack2(acc[ip][1], lo1, hi1);
            unpack2(acc[ip][2], lo2, hi2); unpack2(acc[ip][3], lo3, hi3);
            int b = warp * 8 + 2 * ip;
            float4 r0 = make_float4(lo0 + bias.x, lo1 + bias.y, lo2 + bias.z, lo3 + bias.w);
            float4 r1 = make_float4(hi0 + bias.x, hi1 + bias.y, hi2 + bias.z, hi3 + bias.w);
            *reinterpret_cast<float4*>(g_logits + (size_t)b * VV + v)       = r0;
            *reinterpret_cast<float4*>(g_logits + (size_t)(b + 1) * VV + v) = r1;
        }
    }
}

// ---------------- K8: partial vocab softmax stats (256 blocks) ----------------
__global__ void k_vstats1() {
    __shared__ float sh[8];
    int b = blockIdx.x >> 2, q = blockIdx.x & 3;
    int tid = threadIdx.x, warp = tid >> 5, lane = tid & 31;
    const float* lg = g_logits + (size_t)b * VV;
    int lo = q * 12500, hi = lo + 12500;
    float m = -3.4e38f;
    for (int v = lo + tid; v < hi; v += 256) m = fmaxf(m, lg[v]);
    m = warpMax(m);
    if (lane == 0) sh[warp] = m;
    __syncthreads();
    float mm = sh[0];
#pragma unroll
    for (int i = 1; i < 8; i++) mm = fmaxf(mm, sh[i]);
    __syncthreads();
    float s = 0.f;
    for (int v = lo + tid; v < hi; v += 256) s += __expf(lg[v] - mm);
    s = warpSum(s);
    if (lane == 0) sh[warp] = s;
    __syncthreads();
    if (tid == 0) {
        float tot = 0.f;
#pragma unroll
        for (int i = 0; i < 8; i++) tot += sh[i];
        g_pm[blockIdx.x] = mm;
        g_ps[blockIdx.x] = tot;
    }
}

// ---------------- K9: final vocab part + tail (vstats combine inlined) ----------------
__global__ void __launch_bounds__(256) k_final(float* __restrict__ out,
                                               const float* __restrict__ cov_in,
                                               int out_size) {
    int bid = blockIdx.x;
    if (bid < FINAL_BLOCKS) {
        int b = bid / 198;
        int v = (bid % 198) * 256 + threadIdx.x;
        if (v >= VXX) return;
        // combine the 4 partial stats (L2-resident broadcast)
        float pm0 = g_pm[b*4+0], pm1 = g_pm[b*4+1], pm2 = g_pm[b*4+2], pm3 = g_pm[b*4+3];
        float mm = fmaxf(fmaxf(pm0, pm1), fmaxf(pm2, pm3));
        float tot = g_ps[b*4+0] * __expf(pm0 - mm) + g_ps[b*4+1] * __expf(pm1 - mm)
                  + g_ps[b*4+2] * __expf(pm2 - mm) + g_ps[b*4+3] * __expf(pm3 - mm);
        float scale = g_pgen[b] / tot;
        float val = 0.f;
        if (v < VV) val = __expf(g_logits[(size_t)b * VV + v] - mm) * scale;
        out[(size_t)b * VXX + v] = val;
    } else {
        int i = (bid - FINAL_BLOCKS) * 256 + threadIdx.x;
        int pos = FINAL_N + i;
        if (pos >= out_size) return;
        float v;
        if (i < BB*HH)                       v = g_h[i];
        else if (i < 2*BB*HH)                v = g_c[i - BB*HH];
        else if (i < 2*BB*HH + BB*HH2)       v = g_ct[i - 2*BB*HH];
        else if (i < 2*BB*HH + BB*HH2 + BB*TKK) v = g_attn[i - 2*BB*HH - BB*HH2];
        else if (i < 2*BB*HH + BB*HH2 + BB*TKK + BB) v = g_pgen[i - 2*BB*HH - BB*HH2 - BB*TKK];
        else                                 v = cov_in[i - 2*BB*HH - BB*HH2 - BB*TKK - BB];
        out[pos] = v;
    }
}

// ---------------- K10: scatter-add pointer distribution ----------------
__global__ void k_scatter(float* __restrict__ out, const int* __restrict__ iev) {
    int i = blockIdx.x * 256 + threadIdx.x;
    int b = i & 63, t = i >> 6;
    int idx = iev[t * BB + b];
    float w = (1.f - g_pgen[b]) * g_attn[b * TKK + t];
    atomicAdd(out + (size_t)b * VXX + idx, w);
}

extern "C" void kernel_launch(void* const* d_in, const int* in_sizes, int n_in,
                              void* d_out, int out_size) {
    const int*   ids   = (const int*)  d_in[0];
    const float* h0    = (const float*)d_in[1];
    const float* c0    = (const float*)d_in[2];
    const float* eo    = (const float*)d_in[3];
    const float* ef    = (const float*)d_in[4];
    const float* mask  = (const float*)d_in[5];
    const float* ct1   = (const float*)d_in[6];
    const int*   iev   = (const int*)  d_in[7];
    const float* cov   = (const float*)d_in[8];
    const float* W_emb = (const float*)d_in[10];
    const float* W_ctx = (const float*)d_in[11];
    const float* b_ctx = (const float*)d_in[12];
    const float* W_ih  = (const float*)d_in[13];
    const float* W_hh  = (const float*)d_in[14];
    const float* b_ih  = (const float*)d_in[15];
    const float* b_hh  = (const float*)d_in[16];
    const float* W_attn= (const float*)d_in[17];
    const float* b_attn= (const float*)d_in[18];
    const float* v_attn= (const float*)d_in[19];
    const float* W_pgen= (const float*)d_in[20];
    const float* b_pgen= (const float*)d_in[21];
    const float* W_out1= (const float*)d_in[22];
    const float* b_out1= (const float*)d_in[23];
    const float* W_out2= (const float*)d_in[24];
    const float* b_out2= (const float*)d_in[25];
    float* out = (float*)d_out;

    k_x<<<64, 256>>>(ids, ct1, W_emb, W_ctx, b_ctx);
    k_lstm<<<128, 256>>>(h0, c0, W_ih, W_hh, b_ih, b_hh);
    k_attnfeat<<<256, 256>>>(W_attn, b_attn);
    k_scores<<<1024, 256>>>(reinterpret_cast<const float4*>(ef), v_attn);
    k_ct<<<512, 256>>>(reinterpret_cast<const float4*>(eo), mask);
    k_out1<<<129, 256>>>(W_out1, b_out1, W_pgen, b_pgen);
    k_logits<<<(VV + 127) / 128, 256>>>(W_out2, b_out2);
    k_vstats1<<<256, 256>>>();
    int tail_blocks = (out_size > FINAL_N) ? (out_size - FINAL_N + 255) / 256 : 0;
    k_final<<<FINAL_BLOCKS + tail_blocks, 256>>>(out, cov, out_size);
    k_scatter<<<(BB * TKK) / 256, 256>>>(out, iev);
}